// round 4
// baseline (speedup 1.0000x reference)
#include <cuda_runtime.h>
#include <cuda_bf16.h>
#include <stdint.h>

#define NC 256      // clusters
#define NP 128      // points per cluster
#define VS 32
#define VS3 (VS*VS*VS)

// scratch (allocation-free rule: __device__ globals)
__device__ float g_vox[NC * VS3];            // 32 MB
__device__ float g_c1 [NC * 16 * 4096];      // 64 MB  (conv1, linear, no bias/relu)

// ---------------------------------------------------------------- K1: voxelize
__global__ void __launch_bounds__(128) vox_kernel(
    const float* __restrict__ data, const int* __restrict__ clusts,
    const int* __restrict__ mask)
{
    extern __shared__ float vsh[];           // VS3 floats
    const int c = blockIdx.x;
    const int tid = threadIdx.x;

    float4* v4 = reinterpret_cast<float4*>(vsh);
    #pragma unroll 4
    for (int i = tid; i < VS3/4; i += 128) v4[i] = make_float4(0.f,0.f,0.f,0.f);

    const int p = tid;
    const int idx = clusts[c*NP + p];
    const bool m = mask[c*NP + p] != 0;
    const float px = data[idx*5+0];
    const float py = data[idx*5+1];
    const float pz = data[idx*5+2];
    const float val = data[idx*5+4];

    const float BIG = 1e9f;
    float mn[3], mx[3];
    mn[0] = m ? px :  BIG; mn[1] = m ? py :  BIG; mn[2] = m ? pz :  BIG;
    mx[0] = m ? px : -BIG; mx[1] = m ? py : -BIG; mx[2] = m ? pz : -BIG;
    #pragma unroll
    for (int off = 16; off; off >>= 1) {
        #pragma unroll
        for (int a = 0; a < 3; a++) {
            mn[a] = fminf(mn[a], __shfl_xor_sync(0xffffffffu, mn[a], off));
            mx[a] = fmaxf(mx[a], __shfl_xor_sync(0xffffffffu, mx[a], off));
        }
    }
    __shared__ float wmn[4][3], wmx[4][3];
    __shared__ float smins[3], srng[3], sgs;
    if ((tid & 31) == 0) {
        #pragma unroll
        for (int a = 0; a < 3; a++) { wmn[tid>>5][a] = mn[a]; wmx[tid>>5][a] = mx[a]; }
    }
    __syncthreads();
    if (tid == 0) {
        float rmax = -BIG;
        #pragma unroll
        for (int a = 0; a < 3; a++) {
            float lo = fminf(fminf(wmn[0][a], wmn[1][a]), fminf(wmn[2][a], wmn[3][a]));
            float hi = fmaxf(fmaxf(wmx[0][a], wmx[1][a]), fmaxf(wmx[2][a], wmx[3][a]));
            smins[a] = lo;
            srng[a]  = hi - lo;
            rmax = fmaxf(rmax, hi - lo);
        }
        sgs = 1.0f / (rmax + 1.0f);
    }
    __syncthreads();

    if (m) {
        const float gs = sgs;
        const float ns = 1.0f / 32.0f;
        float v[3];
        v[0] = (px - smins[0] - srng[0]*0.5f - 0.5f) * gs + 0.5f;
        v[1] = (py - smins[1] - srng[1]*0.5f - 0.5f) * gs + 0.5f;
        v[2] = (pz - smins[2] - srng[2]*0.5f - 0.5f) * gs + 0.5f;
        int i0[3], i1[3];
        #pragma unroll
        for (int a = 0; a < 3; a++) {
            i0[a] = max(0,  (int)floorf(v[a] * 32.0f));
            i1[a] = min(31, (int)floorf((v[a] + gs) * 32.0f));
        }
        for (int i = i0[0]; i <= i1[0]; i++) {
            float lo = (float)i * ns;
            float ox = fmaxf(fminf(v[0]+gs, lo+ns) - fmaxf(v[0], lo), 0.f) / gs;
            for (int j = i0[1]; j <= i1[1]; j++) {
                lo = (float)j * ns;
                float oy  = fmaxf(fminf(v[1]+gs, lo+ns) - fmaxf(v[1], lo), 0.f) / gs;
                float pre = val * ox * oy;
                for (int k = i0[2]; k <= i1[2]; k++) {
                    lo = (float)k * ns;
                    float oz = fmaxf(fminf(v[2]+gs, lo+ns) - fmaxf(v[2], lo), 0.f) / gs;
                    atomicAdd(&vsh[(i*32 + j)*32 + k], pre * oz);
                }
            }
        }
    }
    __syncthreads();
    float4* g4 = reinterpret_cast<float4*>(g_vox + (size_t)c * VS3);
    #pragma unroll 4
    for (int i = tid; i < VS3/4; i += 128) g4[i] = v4[i];
}

// ---------------------------------------------------------------- K2: conv1 (linear)
// smem: vox padded [32][32][33] + W1 432 floats
__global__ void __launch_bounds__(512) conv1_kernel(const float* __restrict__ W1)
{
    extern __shared__ float sh[];
    float* vsh = sh;                    // 32*32*33
    float* w1s = sh + 32*32*33;         // 432
    const int c = blockIdx.x;
    const int tid = threadIdx.x;

    const float* gv = g_vox + (size_t)c * VS3;
    for (int i = tid; i < VS3; i += 512) {
        int w = i & 31, h = (i >> 5) & 31, d = i >> 10;
        vsh[(d*32 + h)*33 + w] = gv[i];
    }
    if (tid < 432) w1s[tid] = W1[tid];
    __syncthreads();

    const int od  = tid >> 5;
    const int oh  = (tid >> 1) & 15;
    const int owh = tid & 1;
    float* outp = g_c1 + (size_t)c * 16 * 4096;

    for (int ocg = 0; ocg < 4; ocg++) {
        float acc[4][8];
        #pragma unroll
        for (int o = 0; o < 4; o++)
            #pragma unroll
            for (int i = 0; i < 8; i++) acc[o][i] = 0.f;

        #pragma unroll
        for (int kd = 0; kd < 3; kd++) {
            int d = 2*od + kd;
            #pragma unroll
            for (int kh = 0; kh < 3; kh++) {
                int h = 2*oh + kh;
                bool valid = (d < 32) && (h < 32);
                float xv[17];
                #pragma unroll
                for (int t = 0; t < 17; t++) {
                    int wabs = owh*16 + t;
                    xv[t] = (valid && wabs < 32) ? vsh[(d*32 + h)*33 + wabs] : 0.f;
                }
                #pragma unroll
                for (int o = 0; o < 4; o++) {
                    int oc = ocg*4 + o;
                    #pragma unroll
                    for (int kw = 0; kw < 3; kw++) {
                        float wv = w1s[oc*27 + kd*9 + kh*3 + kw];
                        #pragma unroll
                        for (int i = 0; i < 8; i++)
                            acc[o][i] = fmaf(xv[2*i + kw], wv, acc[o][i]);
                    }
                }
            }
        }
        #pragma unroll
        for (int o = 0; o < 4; o++)
            #pragma unroll
            for (int i = 0; i < 8; i++)
                outp[(ocg*4 + o)*4096 + (od*16 + oh)*16 + owh*8 + i] = acc[o][i];
    }
}

// ---------------------------------------------------------------- K3: per-edge fused
// smem layout (floats):
//   xbuf: 4 ic * [16*16][17]  = 17408     (also overlaid later: zbuf 4096 + pooled 64)
//   ybuf: 32 * 512            = 16384
//   wbuf: 4*27*64             =  6912
#define XB 0
#define YB 17408
#define WB (17408 + 16384)
#define K3_SMEM ((17408 + 16384 + 6912) * 4)

__global__ void __launch_bounds__(512) edge_kernel(
    const int* __restrict__ eidx, int E, int cmax,
    const float* __restrict__ b1, const float* __restrict__ W2,
    const float* __restrict__ b2, const float* __restrict__ W3,
    const float* __restrict__ b3, const float* __restrict__ Wfc,
    const float* __restrict__ bfc, float* __restrict__ out)
{
    extern __shared__ float sh[];
    float* xbuf = sh + XB;
    float* ybuf = sh + YB;
    float* wbuf = sh + WB;
    float* zbuf = sh + XB;          // overlay (xbuf dead by then)
    float* pooled = sh + XB + 4096;

    const int e = blockIdx.x;
    const int tid = threadIdx.x;
    const int ei = min(max(eidx[e], 0), cmax);
    const int ej = min(max(eidx[E + e], 0), cmax);
    const float* ci = g_c1 + (size_t)ei * 16 * 4096;
    const float* cj = g_c1 + (size_t)ej * 16 * 4096;

    const int odh = tid >> 3;        // 0..63  -> (od2, oh2)
    const int ocg = tid & 7;         // 0..7
    const int od2 = odh >> 3, oh2 = odh & 7;

    float acc[4][8];
    #pragma unroll
    for (int o = 0; o < 4; o++)
        #pragma unroll
        for (int w = 0; w < 8; w++) acc[o][w] = 0.f;

    for (int icg = 0; icg < 4; icg++) {
        // stage x = relu(c1[i]+c1[j]+b1) for 4 input channels, padded rows (stride 17)
        #pragma unroll
        for (int r = 0; r < 8; r++) {
            int fi  = tid + r*512;          // float4 index in [4][1024]
            int icl = fi >> 10;
            int s   = (fi & 1023) * 4;
            const float4 a = *reinterpret_cast<const float4*>(ci + (icg*4 + icl)*4096 + s);
            const float4 b = *reinterpret_cast<const float4*>(cj + (icg*4 + icl)*4096 + s);
            const float bb = b1[icg*4 + icl];
            int d = s >> 8, h = (s >> 4) & 15, w = s & 15;
            float* dst = &xbuf[(icl*256 + d*16 + h)*17 + w];
            dst[0] = fmaxf(a.x + b.x + bb, 0.f);
            dst[1] = fmaxf(a.y + b.y + bb, 0.f);
            dst[2] = fmaxf(a.z + b.z + bb, 0.f);
            dst[3] = fmaxf(a.w + b.w + bb, 0.f);
        }
        // stage W2 chunk: [icl][k][oc32]
        for (int i = tid; i < 4*27*32; i += 512) {
            int oc = i & 31, rest = i >> 5, k = rest % 27, icl = rest / 27;
            wbuf[i] = W2[oc*432 + (icg*4 + icl)*27 + k];
        }
        __syncthreads();

        #pragma unroll
        for (int icl = 0; icl < 4; icl++) {
            #pragma unroll
            for (int kd = 0; kd < 3; kd++) {
                int d = 2*od2 + kd;
                #pragma unroll
                for (int kh = 0; kh < 3; kh++) {
                    int h = 2*oh2 + kh;
                    bool valid = (d < 16) && (h < 16);
                    float xv[17];
                    #pragma unroll
                    for (int t = 0; t < 17; t++)
                        xv[t] = (valid && t < 16) ? xbuf[(icl*256 + d*16 + h)*17 + t] : 0.f;
                    #pragma unroll
                    for (int o = 0; o < 4; o++) {
                        #pragma unroll
                        for (int kw = 0; kw < 3; kw++) {
                            float wv = wbuf[(icl*27 + kd*9 + kh*3 + kw)*32 + (o*8 + ocg)];
                            #pragma unroll
                            for (int ow = 0; ow < 8; ow++)
                                acc[o][ow] = fmaf(xv[2*ow + kw], wv, acc[o][ow]);
                        }
                    }
                }
            }
        }
        __syncthreads();
    }

    // y = relu(acc + b2)
    #pragma unroll
    for (int o = 0; o < 4; o++) {
        int oc = o*8 + ocg;
        float bb = b2[oc];
        #pragma unroll
        for (int ow = 0; ow < 8; ow++)
            ybuf[oc*512 + odh*8 + ow] = fmaxf(acc[o][ow] + bb, 0.f);
    }
    __syncthreads();

    // conv3: 64 oc x 4^3 spatial
    const int sp  = tid >> 3;        // 0..63
    const int od3 = sp >> 4, oh3 = (sp >> 2) & 3, ow3 = sp & 3;
    float acc3[8];
    #pragma unroll
    for (int o = 0; o < 8; o++) acc3[o] = 0.f;

    for (int icg = 0; icg < 8; icg++) {
        for (int i = tid; i < 4*27*64; i += 512) {
            int oc = i & 63, rest = i >> 6, k = rest % 27, icl = rest / 27;
            wbuf[i] = W3[oc*864 + (icg*4 + icl)*27 + k];
        }
        __syncthreads();
        #pragma unroll
        for (int icl = 0; icl < 4; icl++) {
            int ic = icg*4 + icl;
            float yv[27];
            #pragma unroll
            for (int kd = 0; kd < 3; kd++)
                #pragma unroll
                for (int kh = 0; kh < 3; kh++)
                    #pragma unroll
                    for (int kw = 0; kw < 3; kw++) {
                        int d = 2*od3 + kd, h = 2*oh3 + kh, w = 2*ow3 + kw;
                        yv[kd*9 + kh*3 + kw] =
                            (d < 8 && h < 8 && w < 8) ? ybuf[ic*512 + d*64 + h*8 + w] : 0.f;
                    }
            #pragma unroll
            for (int o = 0; o < 8; o++) {
                #pragma unroll
                for (int k = 0; k < 27; k++)
                    acc3[o] = fmaf(yv[k], wbuf[(icl*27 + k)*64 + (o*8 + ocg)], acc3[o]);
            }
        }
        __syncthreads();
    }

    // z = relu(acc3 + b3) -> zbuf (overlay on xbuf region; wbuf/ybuf untouched)
    #pragma unroll
    for (int o = 0; o < 8; o++) {
        int oc = o*8 + ocg;
        zbuf[oc*64 + sp] = fmaxf(acc3[o] + b3[oc], 0.f);
    }
    __syncthreads();

    if (tid < 64) {
        float s = 0.f;
        #pragma unroll 8
        for (int q = 0; q < 64; q++) s += zbuf[tid*64 + q];
        pooled[tid] = s * (1.f/64.f);
    }
    __syncthreads();
    if (tid < 64) {
        float a = bfc[tid];
        #pragma unroll 8
        for (int ic = 0; ic < 64; ic++)
            a = fmaf(pooled[ic], Wfc[ic*64 + tid], a);
        out[e*64 + tid] = a;
    }
}

// ---------------------------------------------------------------- launch
extern "C" void kernel_launch(void* const* d_in, const int* in_sizes, int n_in,
                              void* d_out, int out_size)
{
    const float* data   = (const float*)d_in[0];
    const int*   clusts = (const int*)d_in[1];
    const int*   cmask  = (const int*)d_in[2];   // bool stored as 4-byte (int32/float32): nonzero == true
    const int*   eidx   = (const int*)d_in[3];   // int64 downcast to int32 by harness
    const float* W1  = (const float*)d_in[4];
    const float* b1  = (const float*)d_in[5];
    const float* W2  = (const float*)d_in[6];
    const float* b2  = (const float*)d_in[7];
    const float* W3  = (const float*)d_in[8];
    const float* b3  = (const float*)d_in[9];
    const float* Wfc = (const float*)d_in[10];
    const float* bfc = (const float*)d_in[11];
    float* out = (float*)d_out;

    const int C = in_sizes[1] / NP;       // 256
    const int E = in_sizes[3] / 2;        // 1024

    cudaFuncSetAttribute(vox_kernel,   cudaFuncAttributeMaxDynamicSharedMemorySize, VS3*4);
    cudaFuncSetAttribute(conv1_kernel, cudaFuncAttributeMaxDynamicSharedMemorySize, (32*32*33 + 432)*4);
    cudaFuncSetAttribute(edge_kernel,  cudaFuncAttributeMaxDynamicSharedMemorySize, K3_SMEM);

    vox_kernel  <<<C, 128, VS3*4>>>(data, clusts, cmask);
    conv1_kernel<<<C, 512, (32*32*33 + 432)*4>>>(W1);
    edge_kernel <<<E, 512, K3_SMEM>>>(eidx, E, C - 1, b1, W2, b2, W3, b3, Wfc, bfc, out);
}